// round 12
// baseline (speedup 1.0000x reference)
#include <cuda_runtime.h>
#include <math.h>

#define BB 8
#define TT 200
#define UU 100
#define UU1 101
#define VV 1024
#define BLANK (VV - 1)

// scratch: per-cell blank/emit log-probs (device globals; no allocation)
__device__ float g_blank_lp[BB * TT * UU1];   // [b][t][u], u in [0,U1)
__device__ float g_emit_lp[BB * TT * UU];     // [b][t][u], u in [0,U)

// ---------------------------------------------------------------------------
// Kernel 1: per-row logsumexp over V=1024, emit blank_lp / emit_lp.
// One warp per (b,t,u) row of 4KB. 161600 rows total.
// ---------------------------------------------------------------------------
__global__ __launch_bounds__(256) void lse_kernel(
    const float* __restrict__ logits,
    const int* __restrict__ targets)
{
    const int warp = (blockIdx.x * 256 + threadIdx.x) >> 5;  // row index
    const int lane = threadIdx.x & 31;
    // grid sized exactly: no bounds check needed, but keep safe
    if (warp >= BB * TT * UU1) return;

    const int b   = warp / (TT * UU1);
    const int rem = warp % (TT * UU1);
    const int t   = rem / UU1;
    const int u   = rem % UU1;

    const float4* row4 = reinterpret_cast<const float4*>(logits) +
                         (size_t)warp * (VV / 4);

    float4 vals[8];
#pragma unroll
    for (int k = 0; k < 8; k++) vals[k] = row4[lane + 32 * k];

    float m = -INFINITY;
#pragma unroll
    for (int k = 0; k < 8; k++) {
        m = fmaxf(m, fmaxf(fmaxf(vals[k].x, vals[k].y),
                           fmaxf(vals[k].z, vals[k].w)));
    }
#pragma unroll
    for (int o = 16; o; o >>= 1) m = fmaxf(m, __shfl_xor_sync(0xffffffffu, m, o));

    float s = 0.f;
#pragma unroll
    for (int k = 0; k < 8; k++) {
        s += __expf(vals[k].x - m) + __expf(vals[k].y - m) +
             __expf(vals[k].z - m) + __expf(vals[k].w - m);
    }
#pragma unroll
    for (int o = 16; o; o >>= 1) s += __shfl_xor_sync(0xffffffffu, s, o);

    const float lse = m + __logf(s);

    if (lane == 0) {
        const float* rowf = logits + (size_t)warp * VV;
        g_blank_lp[warp] = rowf[BLANK] - lse;     // L1 hit, row just streamed
        if (u < UU) {
            const int tgt = targets[b * UU + u];
            g_emit_lp[(b * TT + t) * UU + u] = rowf[tgt] - lse;
        }
    }
}

// ---------------------------------------------------------------------------
// Kernel 2: anti-diagonal wavefront alpha recursion, one CTA per batch.
// blank/emit planes for the batch live fully in dynamic SMEM (160.8 KB).
//   alpha[t][u] = LSE(alpha[t-1][u] + blank[t-1][u],
//                     alpha[t][u-1] + emit[t][u-1]),  alpha[0][0] = 0
// cost[b] = -(alpha[t_last][u_tl] + blank[t_last][u_tl])
// ---------------------------------------------------------------------------
__global__ __launch_bounds__(128) void alpha_kernel(
    const int* __restrict__ logit_lengths,
    const int* __restrict__ target_lengths,
    float* __restrict__ out)
{
    extern __shared__ float sm[];
    float* blank_s = sm;                 // TT*UU1 floats
    float* emit_s  = sm + TT * UU1;      // TT*UU  floats
    __shared__ float diag[2][128];

    const int b   = blockIdx.x;
    const int tid = threadIdx.x;

    const float* gb = g_blank_lp + (size_t)b * TT * UU1;
    for (int i = tid; i < TT * UU1; i += 128) blank_s[i] = gb[i];
    const float* ge = g_emit_lp + (size_t)b * TT * UU;
    for (int i = tid; i < TT * UU; i += 128) emit_s[i] = ge[i];

    const int t_last = logit_lengths[b] - 1;
    const int u_tl   = target_lengths[b];
    const int d_rec  = t_last + u_tl;

    diag[0][tid] = -1e30f;
    diag[1][tid] = -1e30f;
    __syncthreads();

    float rec = 0.f;
    int cur = 0;
    const int u = tid;

    for (int d = 0; d <= d_rec; d++) {
        float nv = -1e30f;
        const int t = d - u;
        if (u < UU1 && t >= 0 && t < TT) {
            if (d == 0) {
                nv = 0.f;
            } else {
                const float a  = (t >= 1)
                    ? diag[cur][u] + blank_s[(t - 1) * UU1 + u] : -1e30f;
                const float bv = (u >= 1)
                    ? diag[cur][u - 1] + emit_s[t * UU + (u - 1)] : -1e30f;
                const float mx = fmaxf(a, bv);
                const float mn = fminf(a, bv);
                // exp underflows to 0 when mn is the -1e30 sentinel -> nv = mx
                nv = mx + log1pf(__expf(mn - mx));
            }
        }
        diag[cur ^ 1][tid] = nv;
        if (d == d_rec && u == u_tl) rec = nv;
        __syncthreads();
        cur ^= 1;
    }

    if (u == u_tl) {
        out[b] = -(rec + blank_s[t_last * UU1 + u_tl]);
    }
}

// ---------------------------------------------------------------------------
extern "C" void kernel_launch(void* const* d_in, const int* in_sizes, int n_in,
                              void* d_out, int out_size)
{
    const float* logits         = (const float*)d_in[0];
    const int*   targets        = (const int*)d_in[1];
    const int*   logit_lengths  = (const int*)d_in[2];
    const int*   target_lengths = (const int*)d_in[3];
    float* out = (float*)d_out;

    // 161600 rows, 8 warps per 256-thread block
    const int rows = BB * TT * UU1;
    const int blocks = (rows + 7) / 8;   // 20200
    lse_kernel<<<blocks, 256>>>(logits, targets);

    const size_t smem = (size_t)(TT * UU1 + TT * UU) * sizeof(float); // 160800 B
    cudaFuncSetAttribute(alpha_kernel,
                         cudaFuncAttributeMaxDynamicSharedMemorySize,
                         (int)smem);
    alpha_kernel<<<BB, 128, smem>>>(logit_lengths, target_lengths, out);
}

// round 13
// speedup vs baseline: 1.0042x; 1.0042x over previous
#include <cuda_runtime.h>
#include <math.h>

#define BB 8
#define TT 200
#define UU 100
#define UU1 101
#define VV 1024
#define BLANK (VV - 1)

// scratch: per-cell blank/emit log-probs (device globals; no allocation)
__device__ float g_blank_lp[BB * TT * UU1];   // [b][t][u], u in [0,U1)
__device__ float g_emit_lp[BB * TT * UU];     // [b][t][u], u in [0,U)

// ---------------------------------------------------------------------------
// Kernel 1: per-row logsumexp over V=1024, emit blank_lp / emit_lp.
// One warp per (b,t,u) row of 4KB. 161600 rows total.
// ---------------------------------------------------------------------------
__global__ __launch_bounds__(256) void lse_kernel(
    const float* __restrict__ logits,
    const int* __restrict__ targets)
{
    const int warp = (blockIdx.x * 256 + threadIdx.x) >> 5;  // row index
    const int lane = threadIdx.x & 31;
    // grid sized exactly: no bounds check needed, but keep safe
    if (warp >= BB * TT * UU1) return;

    const int b   = warp / (TT * UU1);
    const int rem = warp % (TT * UU1);
    const int t   = rem / UU1;
    const int u   = rem % UU1;

    const float4* row4 = reinterpret_cast<const float4*>(logits) +
                         (size_t)warp * (VV / 4);

    float4 vals[8];
#pragma unroll
    for (int k = 0; k < 8; k++) vals[k] = row4[lane + 32 * k];

    float m = -INFINITY;
#pragma unroll
    for (int k = 0; k < 8; k++) {
        m = fmaxf(m, fmaxf(fmaxf(vals[k].x, vals[k].y),
                           fmaxf(vals[k].z, vals[k].w)));
    }
#pragma unroll
    for (int o = 16; o; o >>= 1) m = fmaxf(m, __shfl_xor_sync(0xffffffffu, m, o));

    float s = 0.f;
#pragma unroll
    for (int k = 0; k < 8; k++) {
        s += __expf(vals[k].x - m) + __expf(vals[k].y - m) +
             __expf(vals[k].z - m) + __expf(vals[k].w - m);
    }
#pragma unroll
    for (int o = 16; o; o >>= 1) s += __shfl_xor_sync(0xffffffffu, s, o);

    const float lse = m + __logf(s);

    if (lane == 0) {
        const float* rowf = logits + (size_t)warp * VV;
        g_blank_lp[warp] = rowf[BLANK] - lse;     // L1 hit, row just streamed
        if (u < UU) {
            const int tgt = targets[b * UU + u];
            g_emit_lp[(b * TT + t) * UU + u] = rowf[tgt] - lse;
        }
    }
}

// ---------------------------------------------------------------------------
// Kernel 2: anti-diagonal wavefront alpha recursion, one CTA per batch.
// blank/emit planes for the batch live fully in dynamic SMEM (160.8 KB).
//   alpha[t][u] = LSE(alpha[t-1][u] + blank[t-1][u],
//                     alpha[t][u-1] + emit[t][u-1]),  alpha[0][0] = 0
// cost[b] = -(alpha[t_last][u_tl] + blank[t_last][u_tl])
// ---------------------------------------------------------------------------
__global__ __launch_bounds__(128) void alpha_kernel(
    const int* __restrict__ logit_lengths,
    const int* __restrict__ target_lengths,
    float* __restrict__ out)
{
    extern __shared__ float sm[];
    float* blank_s = sm;                 // TT*UU1 floats
    float* emit_s  = sm + TT * UU1;      // TT*UU  floats
    __shared__ float diag[2][128];

    const int b   = blockIdx.x;
    const int tid = threadIdx.x;

    const float* gb = g_blank_lp + (size_t)b * TT * UU1;
    for (int i = tid; i < TT * UU1; i += 128) blank_s[i] = gb[i];
    const float* ge = g_emit_lp + (size_t)b * TT * UU;
    for (int i = tid; i < TT * UU; i += 128) emit_s[i] = ge[i];

    const int t_last = logit_lengths[b] - 1;
    const int u_tl   = target_lengths[b];
    const int d_rec  = t_last + u_tl;

    diag[0][tid] = -1e30f;
    diag[1][tid] = -1e30f;
    __syncthreads();

    float rec = 0.f;
    int cur = 0;
    const int u = tid;

    for (int d = 0; d <= d_rec; d++) {
        float nv = -1e30f;
        const int t = d - u;
        if (u < UU1 && t >= 0 && t < TT) {
            if (d == 0) {
                nv = 0.f;
            } else {
                const float a  = (t >= 1)
                    ? diag[cur][u] + blank_s[(t - 1) * UU1 + u] : -1e30f;
                const float bv = (u >= 1)
                    ? diag[cur][u - 1] + emit_s[t * UU + (u - 1)] : -1e30f;
                const float mx = fmaxf(a, bv);
                const float mn = fminf(a, bv);
                // exp underflows to 0 when mn is the -1e30 sentinel -> nv = mx
                nv = mx + log1pf(__expf(mn - mx));
            }
        }
        diag[cur ^ 1][tid] = nv;
        if (d == d_rec && u == u_tl) rec = nv;
        __syncthreads();
        cur ^= 1;
    }

    if (u == u_tl) {
        out[b] = -(rec + blank_s[t_last * UU1 + u_tl]);
    }
}

// ---------------------------------------------------------------------------
extern "C" void kernel_launch(void* const* d_in, const int* in_sizes, int n_in,
                              void* d_out, int out_size)
{
    const float* logits         = (const float*)d_in[0];
    const int*   targets        = (const int*)d_in[1];
    const int*   logit_lengths  = (const int*)d_in[2];
    const int*   target_lengths = (const int*)d_in[3];
    float* out = (float*)d_out;

    // 161600 rows, 8 warps per 256-thread block
    const int rows = BB * TT * UU1;
    const int blocks = (rows + 7) / 8;   // 20200
    lse_kernel<<<blocks, 256>>>(logits, targets);

    const size_t smem = (size_t)(TT * UU1 + TT * UU) * sizeof(float); // 160800 B
    cudaFuncSetAttribute(alpha_kernel,
                         cudaFuncAttributeMaxDynamicSharedMemorySize,
                         (int)smem);
    alpha_kernel<<<BB, 128, smem>>>(logit_lengths, target_lengths, out);
}

// round 14
// speedup vs baseline: 1.0064x; 1.0022x over previous
#include <cuda_runtime.h>
#include <math.h>

#define BB 8
#define TT 200
#define UU 100
#define UU1 101
#define VV 1024
#define BLANK (VV - 1)

// scratch: per-cell blank/emit log-probs (device globals; no allocation)
__device__ float g_blank_lp[BB * TT * UU1];   // [b][t][u], u in [0,U1)
__device__ float g_emit_lp[BB * TT * UU];     // [b][t][u], u in [0,U)

// ---------------------------------------------------------------------------
// Kernel 1: per-row logsumexp over V=1024, emit blank_lp / emit_lp.
// One warp per (b,t,u) row of 4KB. 161600 rows total.
// ---------------------------------------------------------------------------
__global__ __launch_bounds__(256) void lse_kernel(
    const float* __restrict__ logits,
    const int* __restrict__ targets)
{
    const int warp = (blockIdx.x * 256 + threadIdx.x) >> 5;  // row index
    const int lane = threadIdx.x & 31;
    // grid sized exactly: no bounds check needed, but keep safe
    if (warp >= BB * TT * UU1) return;

    const int b   = warp / (TT * UU1);
    const int rem = warp % (TT * UU1);
    const int t   = rem / UU1;
    const int u   = rem % UU1;

    const float4* row4 = reinterpret_cast<const float4*>(logits) +
                         (size_t)warp * (VV / 4);

    float4 vals[8];
#pragma unroll
    for (int k = 0; k < 8; k++) vals[k] = row4[lane + 32 * k];

    float m = -INFINITY;
#pragma unroll
    for (int k = 0; k < 8; k++) {
        m = fmaxf(m, fmaxf(fmaxf(vals[k].x, vals[k].y),
                           fmaxf(vals[k].z, vals[k].w)));
    }
#pragma unroll
    for (int o = 16; o; o >>= 1) m = fmaxf(m, __shfl_xor_sync(0xffffffffu, m, o));

    float s = 0.f;
#pragma unroll
    for (int k = 0; k < 8; k++) {
        s += __expf(vals[k].x - m) + __expf(vals[k].y - m) +
             __expf(vals[k].z - m) + __expf(vals[k].w - m);
    }
#pragma unroll
    for (int o = 16; o; o >>= 1) s += __shfl_xor_sync(0xffffffffu, s, o);

    const float lse = m + __logf(s);

    if (lane == 0) {
        const float* rowf = logits + (size_t)warp * VV;
        g_blank_lp[warp] = rowf[BLANK] - lse;     // L1 hit, row just streamed
        if (u < UU) {
            const int tgt = targets[b * UU + u];
            g_emit_lp[(b * TT + t) * UU + u] = rowf[tgt] - lse;
        }
    }
}

// ---------------------------------------------------------------------------
// Kernel 2: anti-diagonal wavefront alpha recursion, one CTA per batch.
// blank/emit planes for the batch live fully in dynamic SMEM (160.8 KB).
//   alpha[t][u] = LSE(alpha[t-1][u] + blank[t-1][u],
//                     alpha[t][u-1] + emit[t][u-1]),  alpha[0][0] = 0
// cost[b] = -(alpha[t_last][u_tl] + blank[t_last][u_tl])
// ---------------------------------------------------------------------------
__global__ __launch_bounds__(128) void alpha_kernel(
    const int* __restrict__ logit_lengths,
    const int* __restrict__ target_lengths,
    float* __restrict__ out)
{
    extern __shared__ float sm[];
    float* blank_s = sm;                 // TT*UU1 floats
    float* emit_s  = sm + TT * UU1;      // TT*UU  floats
    __shared__ float diag[2][128];

    const int b   = blockIdx.x;
    const int tid = threadIdx.x;

    const float* gb = g_blank_lp + (size_t)b * TT * UU1;
    for (int i = tid; i < TT * UU1; i += 128) blank_s[i] = gb[i];
    const float* ge = g_emit_lp + (size_t)b * TT * UU;
    for (int i = tid; i < TT * UU; i += 128) emit_s[i] = ge[i];

    const int t_last = logit_lengths[b] - 1;
    const int u_tl   = target_lengths[b];
    const int d_rec  = t_last + u_tl;

    diag[0][tid] = -1e30f;
    diag[1][tid] = -1e30f;
    __syncthreads();

    float rec = 0.f;
    int cur = 0;
    const int u = tid;

    for (int d = 0; d <= d_rec; d++) {
        float nv = -1e30f;
        const int t = d - u;
        if (u < UU1 && t >= 0 && t < TT) {
            if (d == 0) {
                nv = 0.f;
            } else {
                const float a  = (t >= 1)
                    ? diag[cur][u] + blank_s[(t - 1) * UU1 + u] : -1e30f;
                const float bv = (u >= 1)
                    ? diag[cur][u - 1] + emit_s[t * UU + (u - 1)] : -1e30f;
                const float mx = fmaxf(a, bv);
                const float mn = fminf(a, bv);
                // exp underflows to 0 when mn is the -1e30 sentinel -> nv = mx
                nv = mx + log1pf(__expf(mn - mx));
            }
        }
        diag[cur ^ 1][tid] = nv;
        if (d == d_rec && u == u_tl) rec = nv;
        __syncthreads();
        cur ^= 1;
    }

    if (u == u_tl) {
        out[b] = -(rec + blank_s[t_last * UU1 + u_tl]);
    }
}

// ---------------------------------------------------------------------------
extern "C" void kernel_launch(void* const* d_in, const int* in_sizes, int n_in,
                              void* d_out, int out_size)
{
    const float* logits         = (const float*)d_in[0];
    const int*   targets        = (const int*)d_in[1];
    const int*   logit_lengths  = (const int*)d_in[2];
    const int*   target_lengths = (const int*)d_in[3];
    float* out = (float*)d_out;

    // 161600 rows, 8 warps per 256-thread block
    const int rows = BB * TT * UU1;
    const int blocks = (rows + 7) / 8;   // 20200
    lse_kernel<<<blocks, 256>>>(logits, targets);

    const size_t smem = (size_t)(TT * UU1 + TT * UU) * sizeof(float); // 160800 B
    cudaFuncSetAttribute(alpha_kernel,
                         cudaFuncAttributeMaxDynamicSharedMemorySize,
                         (int)smem);
    alpha_kernel<<<BB, 128, smem>>>(logit_lengths, target_lengths, out);
}